// round 6
// baseline (speedup 1.0000x reference)
#include <cuda_runtime.h>
#include <cuda_bf16.h>
#include <cstdint>

// Shapes (fixed by the problem)
#define BB      8
#define TIMES   288
#define NNODES  207
#define DD      64
#define TT      288
#define NBT     (BB * TIMES)        // 2304 (b,t) rows
#define REP     69                  // nodes materialized in smem per chunk
#define NCHUNK  3                   // 3 * 69 = 207
#define CHUNK_BYTES (REP * DD * 4)  // 17664 B, 16B-aligned
#define ROW_BYTES   (NNODES * DD * 4) // 52992 B

// STG-based variants all saturate the per-SM L1 store sector pipe
// (32 B/cyc/SM -> 5.06 TB/s chip = observed 24.1us). Route the 122 MB output
// through TMA bulk stores (smem -> gmem), which ride the LTS path
// (~6300 B/cyc chip ≈ 6.9 TB/s) instead of the per-thread store pipe.
__global__ __launch_bounds__(256, 8)
void tememb_kernel(const int*   __restrict__ TE,
                   const float* __restrict__ W1,
                   const float* __restrict__ b1,
                   const float* __restrict__ W2,
                   const float* __restrict__ b2,
                   float*       __restrict__ out)
{
    const int bt  = blockIdx.x;     // 0 .. 2303
    const int tid = threadIdx.x;    // 0 .. 255

    __shared__ float h[DD];
    __shared__ float o[DD];
    __shared__ alignas(16) float row[REP * DD];   // 17664 B

    const int* te = TE + (size_t)bt * (NNODES * 2);   // node 0 of (b,t)

    if (tid < DD) {
        int dow = te[0] % 7;  if (dow < 0) dow += 7;
        int tod = te[1] % TT; if (tod < 0) tod += TT;
        float v = W1[dow * DD + tid] + W1[(7 + tod) * DD + tid] + b1[tid];
        h[tid] = v > 0.f ? v : 0.f;
    }
    __syncthreads();

    if (tid < DD) {
        float acc = b2[tid];
        #pragma unroll
        for (int d = 0; d < DD; ++d)
            acc = fmaf(h[d], W2[d * DD + tid], acc);   // coalesced W2 columns
        o[tid] = acc;
    }
    __syncthreads();

    // Replicate the 64-float result 69x into smem.
    // (j*4) % 64 == (tid & 15)*4 for j = tid + k*256 -> fixed source float4.
    const float4 v4 = reinterpret_cast<const float4*>(o)[tid & 15];
    float4* r4 = reinterpret_cast<float4*>(row);
    constexpr int NV4 = REP * DD / 4;   // 1104
    #pragma unroll
    for (int j = tid; j < NV4; j += 256)
        r4[j] = v4;
    __syncthreads();

    // Make generic-proxy smem writes visible to the async (TMA) proxy.
    asm volatile("fence.proxy.async.shared::cta;" ::: "memory");

    if (tid == 0) {
        uint32_t src;
        asm("{ .reg .u64 t; cvta.to.shared.u64 t, %1; cvt.u32.u64 %0, t; }"
            : "=r"(src) : "l"(row));
        char* dst = reinterpret_cast<char*>(out) + (size_t)bt * ROW_BYTES;
        #pragma unroll
        for (int c = 0; c < NCHUNK; ++c) {
            asm volatile(
                "cp.async.bulk.global.shared::cta.bulk_group [%0], [%1], %2;"
                :: "l"(dst + (size_t)c * CHUNK_BYTES), "r"(src), "r"(CHUNK_BYTES)
                : "memory");
        }
        asm volatile("cp.async.bulk.commit_group;" ::: "memory");
        // Smem may not be reused/freed until TMA has read it.
        asm volatile("cp.async.bulk.wait_group.read 0;" ::: "memory");
    }
    __syncthreads();   // no thread exits (freeing smem) before TMA reads finish
}

extern "C" void kernel_launch(void* const* d_in, const int* in_sizes, int n_in,
                              void* d_out, int out_size)
{
    const int*   TE = (const int*)  d_in[0];
    const float* W1 = (const float*)d_in[1];
    const float* b1 = (const float*)d_in[2];
    const float* W2 = (const float*)d_in[3];
    const float* b2 = (const float*)d_in[4];
    float* out = (float*)d_out;

    tememb_kernel<<<NBT, 256>>>(TE, W1, b1, W2, b2, out);
}

// round 7
// speedup vs baseline: 1.0060x; 1.0060x over previous
#include <cuda_runtime.h>
#include <cuda_bf16.h>
#include <cstdint>

// Shapes (fixed by the problem)
#define BB      8
#define TIMES   288
#define NNODES  207
#define DD      64
#define TT      288
#define NBT     (BB * TIMES)      // 2304 (b,t) rows
#define NV      (NNODES * DD / 4) // 3312 float4 per row (52.9 KB)

// out[b][t][n][:] = (relu(W1[dow] + W1[7+tod] + b1) @ W2 + b2), broadcast over n.
// Verified write-bandwidth-bound: STG.128 / STG.256+evict hints / TMA bulk all
// tie at ~24us = 5.1 TB/s effective fill bandwidth (chip roofline for this
// output size). This variant: plain STG.128 (best measured), 512-thread blocks
// for finer wave-tail granularity.
__global__ __launch_bounds__(512, 4)
void tememb_kernel(const int*   __restrict__ TE,
                   const float* __restrict__ W1,
                   const float* __restrict__ b1,
                   const float* __restrict__ W2,
                   const float* __restrict__ b2,
                   float*       __restrict__ out)
{
    const int bt  = blockIdx.x;     // 0 .. 2303
    const int tid = threadIdx.x;    // 0 .. 511

    __shared__ float h[DD];
    __shared__ float o[DD];

    const int* te = TE + (size_t)bt * (NNODES * 2);   // node 0 of (b,t)

    if (tid < DD) {
        int dow = te[0] % 7;  if (dow < 0) dow += 7;
        int tod = te[1] % TT; if (tod < 0) tod += TT;
        float v = W1[dow * DD + tid] + W1[(7 + tod) * DD + tid] + b1[tid];
        h[tid] = v > 0.f ? v : 0.f;
    }
    __syncthreads();

    if (tid < DD) {
        float acc = b2[tid];
        #pragma unroll
        for (int d = 0; d < DD; ++d)
            acc = fmaf(h[d], W2[d * DD + tid], acc);   // coalesced W2 columns
        o[tid] = acc;
    }
    __syncthreads();

    // (tid + k*512) % 16 == tid % 16 -> each thread's source float4 is fixed.
    const float4 v4 = reinterpret_cast<const float4*>(o)[tid & 15];
    float4* __restrict__ dst = reinterpret_cast<float4*>(out) + (size_t)bt * NV;

    #pragma unroll 4
    for (int j = tid; j < NV; j += 512)
        dst[j] = v4;
}

extern "C" void kernel_launch(void* const* d_in, const int* in_sizes, int n_in,
                              void* d_out, int out_size)
{
    const int*   TE = (const int*)  d_in[0];
    const float* W1 = (const float*)d_in[1];
    const float* b1 = (const float*)d_in[2];
    const float* W2 = (const float*)d_in[3];
    const float* b2 = (const float*)d_in[4];
    float* out = (float*)d_out;

    tememb_kernel<<<NBT, 512>>>(TE, W1, b1, W2, b2, out);
}

// round 8
// speedup vs baseline: 1.0108x; 1.0048x over previous
#include <cuda_runtime.h>
#include <cuda_bf16.h>
#include <cstdint>

// Shapes (fixed by the problem)
#define BB      8
#define TIMES   288
#define NNODES  207
#define DD      64
#define TT      288
#define NBT     (BB * TIMES)      // 2304 (b,t) rows
#define NV      (NNODES * DD / 4) // 3312 float4 per row (52.9 KB)

// out[b][t][n][:] = (relu(W1[dow] + W1[7+tod] + b1) @ W2 + b2), broadcast over n.
//
// Roofline note (measured, R1-R7): six structural variants of the write path
// (STG.128, STG+stcs, 256-bit STG + L2 evict_last/evict_first, TMA bulk store,
// 256/512-thread blocks, 1/2 rows per block) all land at 23.8-24.5us kernel
// time = 5.1 TB/s effective fill bandwidth for the contractual 122 MB fp32
// output. That is the chip's pure-write roofline; compute (<2% fma), occupancy
// (64-87%), and L1/L2 policy are non-binding. This is the best-measured
// structure: one block per (b,t) row, 256 threads, plain STG.128 stream.
__global__ __launch_bounds__(256, 8)
void tememb_kernel(const int*   __restrict__ TE,
                   const float* __restrict__ W1,
                   const float* __restrict__ b1,
                   const float* __restrict__ W2,
                   const float* __restrict__ b2,
                   float*       __restrict__ out)
{
    const int bt  = blockIdx.x;     // 0 .. 2303
    const int tid = threadIdx.x;    // 0 .. 255

    __shared__ float h[DD];
    __shared__ float o[DD];

    // TE is (B, TIMES, N, 2); only node 0 matters (reference slices [:, :, 0, :]).
    const int* te = TE + (size_t)bt * (NNODES * 2);

    if (tid < DD) {
        int dow = te[0] % 7;  if (dow < 0) dow += 7;
        int tod = te[1] % TT; if (tod < 0) tod += TT;
        // one_hot(dow,7) ++ one_hot(tod,288) @ W1  ==  W1[dow] + W1[7+tod]
        float v = W1[dow * DD + tid] + W1[(7 + tod) * DD + tid] + b1[tid];
        h[tid] = v > 0.f ? v : 0.f;
    }
    __syncthreads();

    if (tid < DD) {
        float acc = b2[tid];
        #pragma unroll
        for (int d = 0; d < DD; ++d)
            acc = fmaf(h[d], W2[d * DD + tid], acc);   // coalesced W2 columns
        o[tid] = acc;
    }
    __syncthreads();

    // Broadcast the 64-float result to all 207 nodes (3312 float4 per row).
    // (tid + k*256) % 16 == tid % 16 -> each thread's source float4 is fixed.
    const float4 v4 = reinterpret_cast<const float4*>(o)[tid & 15];
    float4* __restrict__ dst = reinterpret_cast<float4*>(out) + (size_t)bt * NV;

    #pragma unroll 8
    for (int j = tid; j < NV; j += 256)
        dst[j] = v4;
}

extern "C" void kernel_launch(void* const* d_in, const int* in_sizes, int n_in,
                              void* d_out, int out_size)
{
    const int*   TE = (const int*)  d_in[0];
    const float* W1 = (const float*)d_in[1];
    const float* b1 = (const float*)d_in[2];
    const float* W2 = (const float*)d_in[3];
    const float* b2 = (const float*)d_in[4];
    float* out = (float*)d_out;

    tememb_kernel<<<NBT, 256>>>(TE, W1, b1, W2, b2, out);
}

// round 9
// speedup vs baseline: 1.0120x; 1.0012x over previous
#include <cuda_runtime.h>
#include <cuda_bf16.h>
#include <cstdint>

// Shapes (fixed by the problem)
#define BB      8
#define TIMES   288
#define NNODES  207
#define DD      64
#define TT      288
#define NBT     (BB * TIMES)        // 2304 (b,t) rows
#define NV      (NNODES * DD / 4)   // 3312 float4 per row
#define NV8     (NNODES * DD / 8)   // 1656 32B stores per row
#define RESIDENT_ROWS 1800          // ~95 MB hinted L2-resident

// Measured roofline (R1-R8): steady-state dur is pinned at ~26.1-26.9us by the
// DRAM write drain of the contractual 122 MB fp32 output (~4.65 TB/s write-only
// cap); in-kernel time (22.4-24.5us across 6 write-path variants) is already
// below that floor. This final variant = R8's best kernel (unroll-8 STG.128,
// 256 thr, one row/block) + R4's best-dur hint (evict_last on resident rows).
struct v8 { uint32_t r[8]; };

__device__ __forceinline__ void st_evict_last(void* p, const v8& v) {
    asm volatile("st.global.L2::evict_last.v8.b32 [%0], {%1,%2,%3,%4,%5,%6,%7,%8};"
                 :: "l"(p), "r"(v.r[0]), "r"(v.r[1]), "r"(v.r[2]), "r"(v.r[3]),
                    "r"(v.r[4]), "r"(v.r[5]), "r"(v.r[6]), "r"(v.r[7]) : "memory");
}

__global__ __launch_bounds__(256, 8)
void tememb_kernel(const int*   __restrict__ TE,
                   const float* __restrict__ W1,
                   const float* __restrict__ b1,
                   const float* __restrict__ W2,
                   const float* __restrict__ b2,
                   float*       __restrict__ out)
{
    const int bt  = blockIdx.x;     // 0 .. 2303
    const int tid = threadIdx.x;    // 0 .. 255

    __shared__ float h[DD];
    __shared__ float o[DD];

    // TE is (B, TIMES, N, 2); only node 0 matters (reference slices [:, :, 0, :]).
    const int* te = TE + (size_t)bt * (NNODES * 2);

    if (tid < DD) {
        int dow = te[0] % 7;  if (dow < 0) dow += 7;
        int tod = te[1] % TT; if (tod < 0) tod += TT;
        // one_hot(dow,7) ++ one_hot(tod,288) @ W1  ==  W1[dow] + W1[7+tod]
        float v = W1[dow * DD + tid] + W1[(7 + tod) * DD + tid] + b1[tid];
        h[tid] = v > 0.f ? v : 0.f;
    }
    __syncthreads();

    if (tid < DD) {
        float acc = b2[tid];
        #pragma unroll
        for (int d = 0; d < DD; ++d)
            acc = fmaf(h[d], W2[d * DD + tid], acc);   // coalesced W2 columns
        o[tid] = acc;
    }
    __syncthreads();

    if (bt < RESIDENT_ROWS) {
        // 256-bit stores (required width for L2 eviction hints on sm_100a).
        // (j*8) % 64 == (tid&7)*8 for j = tid + k*256 -> fixed 32B source slice.
        v8 val;
        const uint32_t* os = reinterpret_cast<const uint32_t*>(o) + (tid & 7) * 8;
        #pragma unroll
        for (int i = 0; i < 8; ++i) val.r[i] = os[i];

        uint32_t* __restrict__ dst =
            reinterpret_cast<uint32_t*>(out) + (size_t)bt * (NNODES * DD);
        #pragma unroll 4
        for (int j = tid; j < NV8; j += 256)
            st_evict_last(dst + (size_t)j * 8, val);
    } else {
        // Plain STG.128 stream, deep unroll for MLP (R8 winner).
        const float4 v4 = reinterpret_cast<const float4*>(o)[tid & 15];
        float4* __restrict__ dst = reinterpret_cast<float4*>(out) + (size_t)bt * NV;
        #pragma unroll 8
        for (int j = tid; j < NV; j += 256)
            dst[j] = v4;
    }
}

extern "C" void kernel_launch(void* const* d_in, const int* in_sizes, int n_in,
                              void* d_out, int out_size)
{
    const int*   TE = (const int*)  d_in[0];
    const float* W1 = (const float*)d_in[1];
    const float* b1 = (const float*)d_in[2];
    const float* W2 = (const float*)d_in[3];
    const float* b2 = (const float*)d_in[4];
    float* out = (float*)d_out;

    tememb_kernel<<<NBT, 256>>>(TE, W1, b1, W2, b2, out);
}